// round 15
// baseline (speedup 1.0000x reference)
#include <cuda_runtime.h>
#include <cuda_fp16.h>
#include <cstdint>

typedef unsigned int u32;

#define BB   512
#define TT   1024
#define TM1  1023
#define II   32
#define EE   32
#define HH   256
#define KIN  64

#define NCTA 128     // 64 pairs x 2 roles
#define BPB  8
#define NTH  512     // 8 MMA warps + 8 helper warps

#define NTILE_TOT (8*156 + 8*160)   // 2528 (same schedule as R13/R14)

#define XSTR 584
#define HSTR 264

__device__ __align__(1024) __half SCHED[NTILE_TOT * 256];

// pair-exchange buffers + sequence flags (zero-initialized .bss)
__device__ __align__(16) __half EXH0[64][2][2][1024];   // [pair][slot][role][b*128+u_l]
__device__ __align__(16) __half EXH1[64][2][2][1024];
__device__ u32 SEQ0[64][2][2];
__device__ u32 SEQ1[64][2][2];

// ---- prep: identical to R13/R14 ----
__global__ void prep_kernel(const float* __restrict__ wih0, const float* __restrict__ whh0,
                            const float* __restrict__ wih1, const float* __restrict__ whh1,
                            const float* __restrict__ wout)
{
    int idx = blockIdx.x * blockDim.x + threadIdx.x;
    if (idx >= NTILE_TOT * 256) return;
    const int j    = idx & 7;
    const int lane = (idx >> 3) & 31;
    const int tile = idx >> 8;

    int w, r;
    if (tile < 8 * 156) { w = tile / 156; r = tile % 156; }
    else { int t2 = tile - 8 * 156; w = 8 + t2 / 160; r = t2 % 160; }

    const int tq = lane & 3;
    const int il = (lane >> 2) + 8 * ((j >> 1) & 1);
    const int kl = tq * 2 + (j & 1) + 8 * (j >> 2);

    float v;
    if (r < 12) {
        const int kt = r / 3, kind = r % 3;
        v = wih0[(kind * 256 + 16 * w + il) * KIN + kt * 16 + kl];
    } else if (r < 60) {
        const int rr = r - 12, kt = rr / 3, kind = rr % 3;
        v = wih1[(kind * 256 + 16 * w + il) * HH + kt * 16 + kl];
    } else if (r < 108) {
        const int rr = r - 60, kt = rr / 3, kind = rr % 3;
        v = whh0[(kind * 256 + 16 * w + il) * HH + kt * 16 + kl];
    } else if (r < 156) {
        const int rr = r - 108, kt = rr / 3, kind = rr % 3;
        v = whh1[(kind * 256 + 16 * w + il) * HH + kt * 16 + kl];
    } else {
        const int local = r - 156;
        const int kt = 2 * (w - 8) + (local >> 1);
        const int mt = local & 1;
        v = wout[(16 * mt + il) * HH + kt * 16 + kl];
    }
    SCHED[tile * 256 + lane * 8 + j] = __float2half_rn(v);
}

__device__ __forceinline__ float tanha(float x) {
    float y; asm("tanh.approx.f32 %0, %1;" : "=f"(y) : "f"(x)); return y;
}
__device__ __forceinline__ float siga(float x) {
    return fmaf(tanha(0.5f * x), 0.5f, 0.5f);
}
__device__ __forceinline__ void hmma(float* c, uint4 a, u32 b0, u32 b1) {
    asm volatile("mma.sync.aligned.m16n8k16.row.col.f32.f16.f16.f32 "
                 "{%0,%1,%2,%3}, {%4,%5,%6,%7}, {%8,%9}, {%0,%1,%2,%3};"
                 : "+f"(c[0]), "+f"(c[1]), "+f"(c[2]), "+f"(c[3])
                 : "r"(a.x), "r"(a.y), "r"(a.z), "r"(a.w), "r"(b0), "r"(b1));
}
__device__ __forceinline__ uint4 ldg_pin(const __half* p) {
    uint4 v;
    asm("ld.global.nc.L1::evict_last.v4.u32 {%0,%1,%2,%3}, [%4];"
        : "=r"(v.x), "=r"(v.y), "=r"(v.z), "=r"(v.w) : "l"(p));
    return v;
}
__device__ __forceinline__ uint4 ldg_stream(const __half* p) {
    uint4 v;
    asm("ld.global.nc.L1::evict_first.v4.u32 {%0,%1,%2,%3}, [%4];"
        : "=r"(v.x), "=r"(v.y), "=r"(v.z), "=r"(v.w) : "l"(p));
    return v;
}
__device__ __forceinline__ void seq_poll(const u32* p, u32 want) {
    u32 v;
    do {
        asm volatile("ld.acquire.gpu.global.u32 %0, [%1];" : "=r"(v) : "l"(p));
    } while (v != want);
}
__device__ __forceinline__ void seq_store(u32* p, u32 v) {
    asm volatile("st.global.u32 [%0], %1;" :: "l"(p), "r"(v) : "memory");
}
#define MEMBAR_GL() asm volatile("membar.gl;" ::: "memory")
#define BARX(id, cnt) asm volatile("bar.sync %0, %1;" :: "r"(id), "r"(cnt) : "memory")

__global__ void __launch_bounds__(NTH, 1)
arrnn_kernel(const float* __restrict__ X,
             const float* __restrict__ ENC,
             const int*   __restrict__ MASK,
             const float* __restrict__ bih0, const float* __restrict__ bhh0,
             const float* __restrict__ bih1, const float* __restrict__ bhh1,
             const float* __restrict__ bout,
             float* __restrict__ outseq, float* __restrict__ outh1,
             int write_h1)
{
    __shared__ __align__(16) __half XB[BPB * XSTR];
    __shared__ __align__(16) __half H1B[BPB * HSTR];
    __shared__ __align__(16) float  bsm[8 * 256];
    __shared__ __align__(16) float4 PY[16][32];

    const int tid  = threadIdx.x;
    const int wid  = tid >> 5;
    const int lane = tid & 31;
    const int g    = lane >> 2;
    const int tq   = lane & 3;
    const int pair = blockIdx.x >> 1;
    const int R    = blockIdx.x & 1;
    const int Rr   = R ^ 1;
    const int b0g  = pair * BPB;

    // biases into SMEM (all 256 units)
    for (int i = tid; i < 8 * 256; i += NTH) {
        const int k = i >> 8, u = i & 255;
        float v;
        switch (k) {
            case 0: v = bih0[u] + bhh0[u]; break;
            case 1: v = bih0[256 + u] + bhh0[256 + u]; break;
            case 2: v = bih0[512 + u]; break;
            case 3: v = bhh0[512 + u]; break;
            case 4: v = bih1[u] + bhh1[u]; break;
            case 5: v = bih1[256 + u] + bhh1[256 + u]; break;
            case 6: v = bih1[512 + u]; break;
            default: v = bhh1[512 + u]; break;
        }
        bsm[i] = v;
    }

    // init activation buffers, x(0)|enc(1)
    for (int i = tid; i < BPB * 512; i += NTH)
        XB[(i >> 9) * XSTR + 64 + (i & 511)] = __float2half_rn(0.f);
    for (int i = tid; i < BPB * HSTR; i += NTH) H1B[i] = __float2half_rn(0.f);
    for (int i = tid; i < BPB * KIN; i += NTH) {
        const int b = i >> 6, k = i & 63;
        const int gb = b0g + b;
        const float v = (k < II) ? X[((size_t)gb * TT) * II + k]
                                 : ENC[((size_t)gb * TT + 1) * EE + (k - II)];
        XB[b * XSTR + k] = __float2half_rn(v);
    }
    __syncthreads();

    // ---- MMA-warp state (wid < 8) ----
    const int mw  = wid;                 // MMA warp id 0..7
    const int ul1 = 16 * mw + g;         // local unit
    const int ul2 = ul1 + 8;
    const int u1  = R * 128 + ul1;       // global unit
    const int u2  = R * 128 + ul2;
    const int s   = R * 8 + mw;          // schedule stream
    const __half* tpw = SCHED +
        (size_t)((s < 8) ? s * 156 : 8 * 156 + (s - 8) * 160) * 256 + lane * 8;

    // helper-warp state (wid >= 8)
    const int hw = wid - 8;
    const __half* gyp = SCHED + (size_t)(8 * 156 + hw * 160 + 156) * 256 + lane * 8;
    const float bya = (hw == 0 || hw == 1) ? bout[16 * hw + g] : 0.0f;
    const float byb = (hw == 0 || hw == 1) ? bout[16 * hw + g + 8] : 0.0f;

    float h0[4] = {0.f,0.f,0.f,0.f}, h1[4] = {0.f,0.f,0.f,0.f};
    float Cr[4] = {0,0,0,0}, Cz[4] = {0,0,0,0}, Ch[4] = {0,0,0,0};
    float Dr[4] = {0,0,0,0}, Dz[4] = {0,0,0,0}, Dh[4] = {0,0,0,0};

    uint4 pg0, pg1, pg2;
    if (wid < 8) { pg0 = ldg_pin(tpw); pg1 = ldg_pin(tpw + 256); pg2 = ldg_pin(tpw + 512); }

    for (int t = 0; t < TM1; ++t) {
        const int bi = t & 1;
        const int slot = t & 1;
        const u32 want = (u32)(t + 1);

        if (wid < 8) {
            // ===================== MMA WARPS =====================
            const __half* xr = XB + g * XSTR;

            // HEAD: x-part of G0 (kt0-3)
            float Ci[4] = {0.f,0.f,0.f,0.f};
            {
                const u32 b0 = *(const u32*)(xr + 2 * tq);
                const u32 b1 = *(const u32*)(xr + 8 + 2 * tq);
                hmma(Cr, pg0, b0, b1); hmma(Cz, pg1, b0, b1); hmma(Ci, pg2, b0, b1);
            }
            const __half* tp = tpw + 3 * 256;
#pragma unroll
            for (int kt = 1; kt < 4; ++kt) {
                const u32 b0 = *(const u32*)(xr + kt * 16 + 2 * tq);
                const u32 b1 = *(const u32*)(xr + kt * 16 + 8 + 2 * tq);
                uint4 ar = ldg_pin(tp); tp += 256;
                uint4 az = ldg_pin(tp); tp += 256;
                uint4 ai = ldg_pin(tp); tp += 256;
                hmma(Cr, ar, b0, b1); hmma(Cz, az, b0, b1); hmma(Ci, ai, b0, b1);
            }
            uint4 pc0 = ldg_pin(tp);
            uint4 pc1 = ldg_pin(tp + 256);
            uint4 pc2 = ldg_pin(tp + 512);
            tp += 3 * 256;

            // epi0: h0(t) for own units -> XB local half + EXH0
            {
                const float br_a = bsm[u1],       br_b = bsm[u2];
                const float bz_a = bsm[256 + u1], bz_b = bsm[256 + u2];
                const float bi_a = bsm[512 + u1], bi_b = bsm[512 + u2];
                const float bn_a = bsm[768 + u1], bn_b = bsm[768 + u2];
#pragma unroll
                for (int p = 0; p < 4; ++p) {
                    const bool a = (p < 2);
                    const float rr = siga(Cr[p] + (a ? br_a : br_b));
                    const float zz = siga(Cz[p] + (a ? bz_a : bz_b));
                    const float nn = tanha(Ci[p] + (a ? bi_a : bi_b) + rr * (Ch[p] + (a ? bn_a : bn_b)));
                    h0[p] = (1.0f - zz) * nn + zz * h0[p];
                    const __half hv = __float2half_rn(h0[p]);
                    const int b = 2 * tq + (p & 1);
                    XB[b * XSTR + 64 + bi * 256 + (a ? u1 : u2)] = hv;
                    EXH0[pair][slot][R][b * 128 + (a ? ul1 : ul2)] = hv;
                }
            }
            MEMBAR_GL();
            BARX(6, 256);
            if (mw == 0 && lane == 0) seq_store(&SEQ0[pair][slot][R], want);
            BARX(1, NTH);   // BAR-A: full h0(t) in XB

            // GC: Wih1 x h0(t) full
            float Di[4] = {0.f,0.f,0.f,0.f};
            {
                const __half* hb = XB + g * XSTR + 64 + bi * 256;
                {
                    const u32 b0 = *(const u32*)(hb + 2 * tq);
                    const u32 b1 = *(const u32*)(hb + 8 + 2 * tq);
                    hmma(Dr, pc0, b0, b1); hmma(Dz, pc1, b0, b1); hmma(Di, pc2, b0, b1);
                }
#pragma unroll
                for (int kt = 1; kt < 3; ++kt) {
                    const u32 b0 = *(const u32*)(hb + kt * 16 + 2 * tq);
                    const u32 b1 = *(const u32*)(hb + kt * 16 + 8 + 2 * tq);
                    uint4 ar = ldg_pin(tp); tp += 256;
                    uint4 az = ldg_pin(tp); tp += 256;
                    uint4 ai = ldg_pin(tp); tp += 256;
                    hmma(Dr, ar, b0, b1); hmma(Dz, az, b0, b1); hmma(Di, ai, b0, b1);
                }
#pragma unroll 4
                for (int kt = 3; kt < 16; ++kt) {
                    const u32 b0 = *(const u32*)(hb + kt * 16 + 2 * tq);
                    const u32 b1 = *(const u32*)(hb + kt * 16 + 8 + 2 * tq);
                    uint4 ar = ldg_stream(tp); tp += 256;
                    uint4 az = ldg_stream(tp); tp += 256;
                    uint4 ai = ldg_stream(tp); tp += 256;
                    hmma(Dr, ar, b0, b1); hmma(Dz, az, b0, b1); hmma(Di, ai, b0, b1);
                }
            }

            // epi1: h1(t) -> H1B local half + EXH1
            {
                const float br_a = bsm[1024 + u1], br_b = bsm[1024 + u2];
                const float bz_a = bsm[1280 + u1], bz_b = bsm[1280 + u2];
                const float bi_a = bsm[1536 + u1], bi_b = bsm[1536 + u2];
                const float bn_a = bsm[1792 + u1], bn_b = bsm[1792 + u2];
#pragma unroll
                for (int p = 0; p < 4; ++p) {
                    const bool a = (p < 2);
                    const float rr = siga(Dr[p] + (a ? br_a : br_b));
                    const float zz = siga(Dz[p] + (a ? bz_a : bz_b));
                    const float nn = tanha(Di[p] + (a ? bi_a : bi_b) + rr * (Dh[p] + (a ? bn_a : bn_b)));
                    h1[p] = (1.0f - zz) * nn + zz * h1[p];
                    const __half hv = __float2half_rn(h1[p]);
                    const int b = 2 * tq + (p & 1);
                    H1B[b * HSTR + (a ? u1 : u2)] = hv;
                    EXH1[pair][slot][R][b * 128 + (a ? ul1 : ul2)] = hv;
                }
            }
            MEMBAR_GL();
            BARX(6, 256);
            if (mw == 0 && lane == 0) seq_store(&SEQ1[pair][slot][R], want);

            // prefetch tail kt0 (tiles 60-62)
            pg0 = ldg_stream(tpw + 60 * 256);
            pg1 = ldg_stream(tpw + 61 * 256);
            pg2 = ldg_stream(tpw + 62 * 256);
            tp += 3 * 256;
            BARX(2, NTH);   // BAR-B: full h1(t) in H1B

            // TAIL: G0h(t+1) carry
#pragma unroll
            for (int p = 0; p < 4; ++p) { Cr[p] = 0.f; Cz[p] = 0.f; Ch[p] = 0.f; }
            {
                const __half* hb = XB + g * XSTR + 64 + bi * 256;
                {
                    const u32 b0 = *(const u32*)(hb + 2 * tq);
                    const u32 b1 = *(const u32*)(hb + 8 + 2 * tq);
                    hmma(Cr, pg0, b0, b1); hmma(Cz, pg1, b0, b1); hmma(Ch, pg2, b0, b1);
                }
#pragma unroll 4
                for (int kt = 1; kt < 16; ++kt) {
                    const u32 b0 = *(const u32*)(hb + kt * 16 + 2 * tq);
                    const u32 b1 = *(const u32*)(hb + kt * 16 + 8 + 2 * tq);
                    uint4 ar = ldg_stream(tp); tp += 256;
                    uint4 az = ldg_stream(tp); tp += 256;
                    uint4 ah = ldg_stream(tp); tp += 256;
                    hmma(Cr, ar, b0, b1); hmma(Cz, az, b0, b1); hmma(Ch, ah, b0, b1);
                }
            }
            // GB(t+1) carry
#pragma unroll
            for (int p = 0; p < 4; ++p) { Dr[p] = 0.f; Dz[p] = 0.f; Dh[p] = 0.f; }
            {
                const __half* hr = H1B + g * HSTR;
#pragma unroll 4
                for (int kt = 0; kt < 16; ++kt) {
                    const u32 b0 = *(const u32*)(hr + kt * 16 + 2 * tq);
                    const u32 b1 = *(const u32*)(hr + kt * 16 + 8 + 2 * tq);
                    uint4 ar = ldg_stream(tp); tp += 256;
                    uint4 az = ldg_stream(tp); tp += 256;
                    uint4 ah = ldg_stream(tp); tp += 256;
                    hmma(Dr, ar, b0, b1); hmma(Dz, az, b0, b1); hmma(Dh, ah, b0, b1);
                }
            }
            pg0 = ldg_pin(tpw); pg1 = ldg_pin(tpw + 256); pg2 = ldg_pin(tpw + 512);
            BARX(3, NTH);   // BAR-C
        } else {
            // ===================== HELPER WARPS =====================
            int kp0 = 0, kp1 = 0;
            float xpre[4];
            if (hw < 2) {   // mask/X prefetch for t+1
                kp0 = MASK[(b0g + 2 * tq) * TT + (t + 1)];
                kp1 = MASK[(b0g + 2 * tq + 1) * TT + (t + 1)];
#pragma unroll
                for (int p = 0; p < 4; ++p) {
                    const int i = 16 * hw + g + ((p < 2) ? 0 : 8);
                    const int b = 2 * tq + (p & 1);
                    xpre[p] = X[((size_t)(b0g + b) * TT + (t + 1)) * II + i];
                }
            }
            if (hw == 2 || hw == 3) {   // fetch partner h0 -> XB
                seq_poll(&SEQ0[pair][slot][Rr], want);
                const __half* src = &EXH0[pair][slot][Rr][0];
                const int t2 = (hw - 2) * 32 + lane;
#pragma unroll
                for (int c = 0; c < 2; ++c) {
                    const int idx = t2 * 2 + c;
                    const int b = idx >> 4, ch = idx & 15;
                    const uint4 v = *(const uint4*)(src + b * 128 + ch * 8);
                    *(uint4*)(&XB[b * XSTR + 64 + bi * 256 + Rr * 128 + ch * 8]) = v;
                }
            }
            BARX(1, NTH);   // BAR-A

            if (hw == 4 || hw == 5) {   // fetch partner h1 -> H1B
                seq_poll(&SEQ1[pair][slot][Rr], want);
                const __half* src = &EXH1[pair][slot][Rr][0];
                const int t2 = (hw - 4) * 32 + lane;
#pragma unroll
                for (int c = 0; c < 2; ++c) {
                    const int idx = t2 * 2 + c;
                    const int b = idx >> 4, ch = idx & 15;
                    const uint4 v = *(const uint4*)(src + b * 128 + ch * 8);
                    *(uint4*)(&H1B[b * HSTR + Rr * 128 + ch * 8]) = v;
                }
            }
            BARX(2, NTH);   // BAR-B

            // GY partials on full h1
            {
                float Ym[8] = {0,0,0,0,0,0,0,0};
                const __half* hr = H1B + g * HSTR;
                const int kbase = 2 * hw;
#pragma unroll
                for (int l = 0; l < 4; ++l) {
                    const int kt = kbase + (l >> 1);
                    uint4 ay = ldg_stream(gyp + l * 256);
                    const u32 b0 = *(const u32*)(hr + kt * 16 + 2 * tq);
                    const u32 b1 = *(const u32*)(hr + kt * 16 + 8 + 2 * tq);
                    hmma(Ym + 4 * (l & 1), ay, b0, b1);
                }
                PY[hw * 2 + 0][lane] = make_float4(Ym[0], Ym[1], Ym[2], Ym[3]);
                PY[hw * 2 + 1][lane] = make_float4(Ym[4], Ym[5], Ym[6], Ym[7]);
            }
            if (hw == 6 || hw == 7) {   // enc(t+2) for next head
                const int i2 = (hw - 6) * 32 + lane;          // 0..63
#pragma unroll
                for (int c = 0; c < 4; ++c) {
                    const int e = i2 * 4 + c;                 // 0..255
                    const int b = e >> 5, k = e & 31;
                    const int eidx = (t + 2 < TT) ? (t + 2) : (TT - 1);
                    XB[b * XSTR + 32 + k] =
                        __float2half_rn(ENC[((size_t)(b0g + b) * TT + eidx) * EE + k]);
                }
            }
            BARX(7, 256);   // helpers: GY partials published
            if (hw < 2) {   // reduce + y + feedback x
                float Y0 = 0.f, Y1 = 0.f, Y2 = 0.f, Y3 = 0.f;
#pragma unroll
                for (int w = 0; w < 8; ++w) {
                    const float4 v = PY[w * 2 + hw][lane];
                    Y0 += v.x; Y1 += v.y; Y2 += v.z; Y3 += v.w;
                }
                float Y[4] = {Y0, Y1, Y2, Y3};
#pragma unroll
                for (int p = 0; p < 4; ++p) {
                    const bool a = (p < 2);
                    const int i = 16 * hw + g + (a ? 0 : 8);
                    const int b = 2 * tq + (p & 1);
                    const float y = Y[p] + (a ? bya : byb);
                    const bool keep = ((p & 1) ? kp1 : kp0) != 0;
                    XB[b * XSTR + i] = __float2half_rn(keep ? xpre[p] : y);
                    if (R == 0)
                        outseq[((size_t)(b0g + b) * TM1 + t) * II + i] = y;
                }
            }
            BARX(3, NTH);   // BAR-C
        }
    }

    // final h1: each role writes its own 128 units
    if (write_h1 && wid < 8) {
#pragma unroll
        for (int p = 0; p < 4; ++p) {
            const int b = b0g + 2 * tq + (p & 1);
            const int u = (p < 2) ? u1 : u2;
            outh1[(size_t)b * HH + u] = h1[p];
        }
    }
}

extern "C" void kernel_launch(void* const* d_in, const int* in_sizes, int n_in,
                              void* d_out, int out_size) {
    const float* X    = (const float*)d_in[0];
    const float* ENC  = (const float*)d_in[1];
    const int*   MASK = (const int*)d_in[2];
    const float* wih0 = (const float*)d_in[3];
    const float* whh0 = (const float*)d_in[4];
    const float* bih0 = (const float*)d_in[5];
    const float* bhh0 = (const float*)d_in[6];
    const float* wih1 = (const float*)d_in[7];
    const float* whh1 = (const float*)d_in[8];
    const float* bih1 = (const float*)d_in[9];
    const float* bhh1 = (const float*)d_in[10];
    const float* wout = (const float*)d_in[11];
    const float* bout = (const float*)d_in[12];

    float* outseq = (float*)d_out;
    const int seqsz = BB * TM1 * II;
    float* outh1  = outseq + seqsz;
    const int write_h1 = (out_size >= seqsz + BB * HH) ? 1 : 0;

    prep_kernel<<<(NTILE_TOT * 256 + 255) / 256, 256>>>(wih0, whh0, wih1, whh1, wout);

    arrnn_kernel<<<NCTA, NTH>>>(X, ENC, MASK,
                                bih0, bhh0, bih1, bhh1, bout,
                                outseq, outh1, write_h1);
}